// round 6
// baseline (speedup 1.0000x reference)
#include <cuda_runtime.h>

#define PP    35
#define CIN   7
#define C1    16
#define A1C   32
#define C2    64
#define A2C   128
#define C3    128
#define DD    10
#define HH    200
#define WWG   176
#define VMAX  20000
#define NBUCK 64
#define NCH   (C1 + C2 + C3)   // 208
#define NP1   20
#define T2    288              // vfe2 threads (9 warps)
#define GRID2 296              // 2 CTAs/SM * 148

typedef unsigned long long ull;

// ---------------- scratch ---------------------------------------------------------
__device__ float  g_h2[(size_t)VMAX * PP * C2];    // pre-BN h2
__device__ float  g_keep[(size_t)VMAX * PP];
__device__ float  g_max3[(size_t)VMAX * C3];
__device__ float  g_min3[(size_t)VMAX * C3];
__device__ double g_sumB [NBUCK][NCH];
__device__ double g_sqB  [NBUCK][NCH];
__device__ float  g_scale[NCH];
__device__ float  g_shift[NCH];

// ---------------- f32x2 helpers ----------------------------------------------------
__device__ __forceinline__ ull pack2(float lo, float hi) {
    ull r;
    asm("mov.b64 %0, {%1, %2};" : "=l"(r) : "f"(lo), "f"(hi));
    return r;
}
__device__ __forceinline__ float2 unpack2(ull v) {
    float2 r;
    asm("mov.b64 {%0, %1}, %2;" : "=f"(r.x), "=f"(r.y) : "l"(v));
    return r;
}
__device__ __forceinline__ void fma2(ull& d, ull a, ull b) {
    asm("fma.rn.f32x2 %0, %1, %2, %0;" : "+l"(d) : "l"(a), "l"(b));
}
__device__ __forceinline__ void add2(ull& d, ull a) {
    asm("add.rn.f32x2 %0, %0, %1;" : "+l"(d) : "l"(a));
}

// ---------------- zero stat buckets ------------------------------------------------
__global__ void k_zero_stats() {
    int n = NBUCK * NCH;
    for (int i = blockIdx.x * blockDim.x + threadIdx.x; i < n; i += gridDim.x * blockDim.x) {
        ((double*)g_sumB)[i] = 0.0;
        ((double*)g_sqB)[i]  = 0.0;
    }
}

// ---------------- pass 1: stats of h1 ---------------------------------------------
__global__ void k_stats1(const float* __restrict__ x,
                         const float* __restrict__ W1,
                         const float* __restrict__ b1, int V) {
    int N = V * PP;
    float lsum[C1], lsq[C1];
    #pragma unroll
    for (int u = 0; u < C1; u++) { lsum[u] = 0.f; lsq[u] = 0.f; }
    for (int r = blockIdx.x * blockDim.x + threadIdx.x; r < N; r += gridDim.x * blockDim.x) {
        float xv[CIN];
        #pragma unroll
        for (int c = 0; c < CIN; c++) xv[c] = x[(size_t)r * CIN + c];
        #pragma unroll
        for (int u = 0; u < C1; u++) {
            float h = b1[u];
            #pragma unroll
            for (int c = 0; c < CIN; c++) h = fmaf(xv[c], W1[c * C1 + u], h);
            lsum[u] += h; lsq[u] += h * h;
        }
    }
    __shared__ float ssum[C1], ssq[C1];
    if (threadIdx.x < C1) { ssum[threadIdx.x] = 0.f; ssq[threadIdx.x] = 0.f; }
    __syncthreads();
    #pragma unroll
    for (int u = 0; u < C1; u++) { atomicAdd(&ssum[u], lsum[u]); atomicAdd(&ssq[u], lsq[u]); }
    __syncthreads();
    if (threadIdx.x < C1) {
        int b = blockIdx.x & (NBUCK - 1);
        atomicAdd(&g_sumB[b][threadIdx.x], (double)ssum[threadIdx.x]);
        atomicAdd(&g_sqB [b][threadIdx.x], (double)ssq [threadIdx.x]);
    }
}

// ---------------- finalize BN params -----------------------------------------------
__global__ void k_finalize(const float* __restrict__ g, const float* __restrict__ be,
                           int off, int nc, double invN) {
    int u = threadIdx.x;
    if (u < nc) {
        double s = 0.0, q = 0.0;
        for (int b = 0; b < NBUCK; b++) { s += g_sumB[b][off + u]; q += g_sqB[b][off + u]; }
        double m   = s * invN;
        double var = q * invN - m * m;
        float  sc  = g[u] * rsqrtf((float)var + 1e-5f);
        g_scale[off + u] = sc;
        g_shift[off + u] = (float)((double)be[u] - m * (double)sc);
    }
}

// ---------------- pass 2: BN1+relu, max; HALVED h2 GEMM -> g_h2 -------------------
__global__ void __launch_bounds__(128) k_vfe1(const float* __restrict__ x,
                       const float* __restrict__ W1, const float* __restrict__ b1,
                       const float* __restrict__ W2, const float* __restrict__ b2, int V) {
    int v = blockIdx.x;
    if (v >= V) return;
    int t = threadIdx.x;

    __shared__ float  s_x[PP * CIN];
    __shared__ float  s_keep[PP + 1];
    __shared__ float  s_h1[PP * C1];
    __shared__ float  s_m1[C1];
    __shared__ float  s_C[C2];
    __shared__ float2 s_a1p[C1 * NP1];
    __shared__ float  s_w2[A1C * C2];
    __shared__ float  s_rs[4 * C2], s_rq[4 * C2];

    const float* xb = x + (size_t)v * (PP * CIN);
    for (int i = t; i < PP * CIN; i += 128) s_x[i] = xb[i];
    for (int i = t; i < A1C * C2; i += 128) s_w2[i] = W2[i];
    __syncthreads();

    if (t < PP) {
        float s = 0.f;
        #pragma unroll
        for (int c = 0; c < CIN; c++) s += s_x[t * CIN + c];
        float k = (s != 0.0f) ? 1.0f : 0.0f;
        s_keep[t] = k;
        g_keep[(size_t)v * PP + t] = k;
    }
    __syncthreads();

    for (int i = t; i < PP * C1; i += 128) {
        int p = i >> 4, u = i & 15;
        float h = b1[u];
        #pragma unroll
        for (int c = 0; c < CIN; c++) h = fmaf(s_x[p * CIN + c], W1[c * C1 + u], h);
        h = fmaf(h, g_scale[u], g_shift[u]);
        s_h1[i] = fmaxf(h, 0.0f);
    }
    __syncthreads();

    if (t < C1) {
        float m = s_h1[t];
        #pragma unroll 7
        for (int p = 1; p < PP; p++) m = fmaxf(m, s_h1[p * C1 + t]);
        s_m1[t] = m;
    }
    __syncthreads();

    for (int i = t; i < C1 * NP1; i += 128) {
        int k = i / NP1, pr = i % NP1;
        int p0 = 2 * pr, p1 = p0 + 1;
        float u0 = 0.f, u1 = 0.f;
        if (p0 < PP) u0 = s_h1[p0 * C1 + k] * s_keep[p0];
        if (p1 < PP) u1 = s_h1[p1 * C1 + k] * s_keep[p1];
        s_a1p[i] = make_float2(u0, u1);
    }
    if (t < C2) {
        float c = 0.f;
        #pragma unroll
        for (int k = 0; k < C1; k++) c = fmaf(s_m1[k], s_w2[(C1 + k) * C2 + t], c);
        s_C[t] = c;
    }
    __syncthreads();

    int lane = t & 31, pg = t >> 5;
    int og = lane * 2;
    ull acc[5][2];
    #pragma unroll
    for (int n = 0; n < 5; n++) { acc[n][0] = 0ULL; acc[n][1] = 0ULL; }

    #pragma unroll 4
    for (int k = 0; k < C1; k++) {
        float2 w = *(const float2*)&s_w2[k * C2 + og];
        ull w0 = pack2(w.x, w.x), w1 = pack2(w.y, w.y);
        const ull* ap = (const ull*)&s_a1p[k * NP1 + pg * 5];
        #pragma unroll
        for (int n = 0; n < 5; n++) {
            ull a = ap[n];
            fma2(acc[n][0], a, w0);
            fma2(acc[n][1], a, w1);
        }
    }

    float C0 = s_C[og], C1v = s_C[og + 1];
    float b0 = b2[og],  b1s = b2[og + 1];
    float ls0 = 0.f, lq0 = 0.f, ls1 = 0.f, lq1 = 0.f;
    float* h2g = g_h2 + (size_t)v * (PP * C2);
    #pragma unroll
    for (int n = 0; n < 5; n++) {
        int pr = pg * 5 + n;
        if (pr < 18) {
            int p0 = 2 * pr, p1 = p0 + 1;
            float2 r0 = unpack2(acc[n][0]);
            float2 r1 = unpack2(acc[n][1]);
            float k0 = s_keep[p0];
            float h00 = fmaf(k0, r0.x + C0,  b0);
            float h01 = fmaf(k0, r1.x + C1v, b1s);
            *(float2*)&h2g[p0 * C2 + og] = make_float2(h00, h01);
            ls0 += h00; lq0 += h00 * h00;
            ls1 += h01; lq1 += h01 * h01;
            if (p1 < PP) {
                float k1 = s_keep[p1];
                float h10 = fmaf(k1, r0.y + C0,  b0);
                float h11 = fmaf(k1, r1.y + C1v, b1s);
                *(float2*)&h2g[p1 * C2 + og] = make_float2(h10, h11);
                ls0 += h10; lq0 += h10 * h10;
                ls1 += h11; lq1 += h11 * h11;
            }
        }
    }
    s_rs[pg * C2 + og] = ls0; s_rs[pg * C2 + og + 1] = ls1;
    s_rq[pg * C2 + og] = lq0; s_rq[pg * C2 + og + 1] = lq1;
    __syncthreads();
    if (t < C2) {
        float S = s_rs[t] + s_rs[C2 + t] + s_rs[2 * C2 + t] + s_rs[3 * C2 + t];
        float Q = s_rq[t] + s_rq[C2 + t] + s_rq[2 * C2 + t] + s_rq[3 * C2 + t];
        int b = v & (NBUCK - 1);
        atomicAdd(&g_sumB[b][C1 + t], (double)S);
        atomicAdd(&g_sqB [b][C1 + t], (double)Q);
    }
}

// ---------------- pass 3: persistent; broadcast-weight GEMM, k-split --------------
// phys channel permutation: o = oc*16 + q*4 + r  <->  phys = q*32 + oc*4 + r
#define HB_S   65
#define H3_S   132
#define F_WA   0                        // [64][128] Wd rows 0..63 (phys)
#define F_WB   8192                     // [64][128] Wd rows 64..127 (phys)
#define F_HB   16384                    // [36][65]
#define F_H3   18728                    // [35][132]  (aliased as partial buffer)
#define F_B    23348
#define F_BD   23476
#define F_M2   23604
#define F_MM   23668
#define F_KEEP 23796
#define F_SC   23836
#define F_SH   23900
#define F_END  23964
#define SM2_BYTES (F_END * 4)

__global__ void __launch_bounds__(T2, 2) k_vfe2(const float4* __restrict__ Wd4,
                                                const float*  __restrict__ bd, int V) {
    extern __shared__ float sm2[];
    float* s_wA   = sm2 + F_WA;
    float* s_wB   = sm2 + F_WB;
    float* s_hb   = sm2 + F_HB;
    float* s_h3   = sm2 + F_H3;
    float* s_B    = sm2 + F_B;
    float* s_bd   = sm2 + F_BD;
    float* s_m2   = sm2 + F_M2;
    float* s_mm   = sm2 + F_MM;
    float* s_keep = sm2 + F_KEEP;
    float* s_sc   = sm2 + F_SC;
    float* s_sh   = sm2 + F_SH;
    ulonglong2* s_part = (ulonglong2*)s_h3;

    int t = threadIdx.x;
    int oc   = t & 7;                       // output chunk (16 outputs)
    int s    = t >> 3;                      // 0..35
    int pair = (s < 18) ? s : s - 18;
    int kb   = (s < 18) ? 0 : 32;           // k-half base
    int p0   = 2 * pair, p1 = p0 + 1;

    // ---- one-time staging: Wd (phys-permuted), bd (phys), BN2 params, pads ----
    for (int i = t; i < A2C * 32; i += T2) {
        int k = i >> 5, c = i & 31;
        float4 wv = Wd4[i];
        int base = (c & 3) * 32 + (c >> 2) * 4;
        float* dst = (k < 64) ? (s_wA + k * 128 + base) : (s_wB + (k - 64) * 128 + base);
        *(float4*)dst = wv;
    }
    if (t < 128) {
        int o = t, oq = (o & 15) >> 2, r4 = o & 3, occ = o >> 4;
        s_bd[oq * 32 + occ * 4 + r4] = bd[o];
    }
    if (t < C2) { s_sc[t] = g_scale[C1 + t]; s_sh[t] = g_shift[C1 + t]; }
    if (t < HB_S) s_hb[35 * HB_S + t] = 0.f;    // pad point 35 stays zero
    __syncthreads();

    for (int v = blockIdx.x; v < V; v += gridDim.x) {
        // ---- phase 1: keep + h2 load + BN2 + relu -> s_hb ----
        if (t < 40) s_keep[t] = (t < PP) ? g_keep[(size_t)v * PP + t] : 0.f;
        const float4* h2g4 = (const float4*)(g_h2 + (size_t)v * (PP * C2));
        for (int i = t; i < (PP * C2) / 4; i += T2) {
            float4 h = h2g4[i];
            int p = i >> 4, u = (i & 15) * 4;
            float* dst = s_hb + p * HB_S + u;
            dst[0] = fmaxf(fmaf(h.x, s_sc[u],     s_sh[u]),     0.f);
            dst[1] = fmaxf(fmaf(h.y, s_sc[u + 1], s_sh[u + 1]), 0.f);
            dst[2] = fmaxf(fmaf(h.z, s_sc[u + 2], s_sh[u + 2]), 0.f);
            dst[3] = fmaxf(fmaf(h.w, s_sc[u + 3], s_sh[u + 3]), 0.f);
        }
        __syncthreads();

        // ---- phase 2: partial column max ----
        if (t < 128) {
            int ch = t & 63, half = t >> 6;
            int pb = half * 18, pe = half ? PP : 18;
            float m = -3.4e38f;
            for (int p = pb; p < pe; p++) m = fmaxf(m, s_hb[p * HB_S + ch]);
            s_mm[half * 64 + ch] = m;
        }
        __syncthreads();

        // ---- phase 3: combine max; fold keep into hb ----
        if (t < C2) s_m2[t] = fmaxf(s_mm[t], s_mm[64 + t]);
        for (int i = t; i < PP * C2; i += T2) {
            int p = i >> 6, u = i & 63;
            s_hb[p * HB_S + u] *= s_keep[p];
        }
        __syncthreads();

        // ---- phase 4: B vector (phys space) + GEMM k-half ----
        if (t < 128) {
            float bsum = 0.f;
            #pragma unroll 8
            for (int k = 0; k < 64; k++)
                bsum = fmaf(s_m2[k], s_wB[k * 128 + t], bsum);
            s_B[t] = bsum;
        }

        ull acc0[4][2], acc1[4][2];
        #pragma unroll
        for (int q = 0; q < 4; q++) {
            acc0[q][0] = 0ULL; acc0[q][1] = 0ULL;
            acc1[q][0] = 0ULL; acc1[q][1] = 0ULL;
        }
        {
            const float* hb0 = s_hb + p0 * HB_S + kb;
            const float* hb1 = s_hb + p1 * HB_S + kb;
            const float* wb  = s_wA + kb * 128 + oc * 4;
            #pragma unroll 4
            for (int kk = 0; kk < 32; kk++) {
                float a0 = hb0[kk], a1 = hb1[kk];
                ull ap0 = pack2(a0, a0), ap1 = pack2(a1, a1);
                const ulonglong2* wrow = (const ulonglong2*)(wb + kk * 128);
                #pragma unroll
                for (int q = 0; q < 4; q++) {
                    ulonglong2 w = wrow[q * 8];
                    fma2(acc0[q][0], ap0, w.x); fma2(acc0[q][1], ap0, w.y);
                    fma2(acc1[q][0], ap1, w.x); fma2(acc1[q][1], ap1, w.y);
                }
            }
        }
        __syncthreads();   // hb/B done being read? (B read later; hb no longer needed)

        // ---- phase 5: upper half stores partials (into h3-aliased buffer) ----
        if (s >= 18) {
            ulonglong2* dst = s_part + (size_t)(pair * 8 + oc) * 8;
            #pragma unroll
            for (int q = 0; q < 4; q++) {
                ulonglong2 v0; v0.x = acc0[q][0]; v0.y = acc0[q][1];
                ulonglong2 v1; v1.x = acc1[q][0]; v1.y = acc1[q][1];
                dst[q]     = v0;
                dst[4 + q] = v1;
            }
        }
        __syncthreads();

        // ---- phase 6: lower half reduces + epilogue (into registers) ----
        if (s < 18) {
            float kp0 = s_keep[p0], kp1 = s_keep[p1];
            ull kpp0 = pack2(kp0, kp0), kpp1 = pack2(kp1, kp1);
            const ulonglong2* src = s_part + (size_t)(pair * 8 + oc) * 8;
            #pragma unroll
            for (int q = 0; q < 4; q++) {
                ulonglong2 pa = src[q];
                ulonglong2 pb = src[4 + q];
                add2(acc0[q][0], pa.x); add2(acc0[q][1], pa.y);
                add2(acc1[q][0], pb.x); add2(acc1[q][1], pb.y);
                ulonglong2 Bq  = *(const ulonglong2*)&s_B [q * 32 + oc * 4];
                ulonglong2 bdq = *(const ulonglong2*)&s_bd[q * 32 + oc * 4];
                fma2(acc0[q][0], Bq.x, kpp0); fma2(acc0[q][1], Bq.y, kpp0);
                fma2(acc1[q][0], Bq.x, kpp1); fma2(acc1[q][1], Bq.y, kpp1);
                add2(acc0[q][0], bdq.x); add2(acc0[q][1], bdq.y);
                add2(acc1[q][0], bdq.x); add2(acc1[q][1], bdq.y);
            }
        }
        __syncthreads();   // partial buffer free; now write h3 into same region

        // ---- phase 7: write h3 tile (phys layout) ----
        if (s < 18) {
            ulonglong2* d0 = (ulonglong2*)(s_h3 + p0 * H3_S + oc * 4);
            #pragma unroll
            for (int q = 0; q < 4; q++) {
                ulonglong2 v; v.x = acc0[q][0]; v.y = acc0[q][1];
                d0[q * 8] = v;
            }
            if (p1 < PP) {
                ulonglong2* d1 = (ulonglong2*)(s_h3 + p1 * H3_S + oc * 4);
                #pragma unroll
                for (int q = 0; q < 4; q++) {
                    ulonglong2 v; v.x = acc1[q][0]; v.y = acc1[q][1];
                    d1[q * 8] = v;
                }
            }
        }
        __syncthreads();

        // ---- phase 8: stats over 35 points (phys col t -> true channel o) ----
        if (t < C3) {
            float S = 0.f, Q = 0.f, MX = -3.4e38f, MN = 3.4e38f;
            #pragma unroll 7
            for (int p = 0; p < PP; p++) {
                float val = s_h3[p * H3_S + t];
                S += val; Q = fmaf(val, val, Q);
                MX = fmaxf(MX, val); MN = fminf(MN, val);
            }
            int q = t >> 5, rem = t & 31;
            int o = (rem >> 2) * 16 + q * 4 + (rem & 3);
            g_max3[(size_t)v * C3 + o] = MX;
            g_min3[(size_t)v * C3 + o] = MN;
            int b = v & (NBUCK - 1);
            atomicAdd(&g_sumB[b][C1 + C2 + o], (double)S);
            atomicAdd(&g_sqB [b][C1 + C2 + o], (double)Q);
        }
        __syncthreads();
    }
}

// ---------------- pass 4: BN3 + relu + max (via max/min) + scatter-add ------------
__global__ void k_scatter(const int* __restrict__ coord, float* __restrict__ out, int V) {
    int v = blockIdx.x;
    if (v >= V) return;
    int u = threadIdx.x;
    float sc = g_scale[C1 + C2 + u];
    float sh = g_shift[C1 + C2 + u];
    float h  = (sc >= 0.0f) ? g_max3[(size_t)v * C3 + u] : g_min3[(size_t)v * C3 + u];
    float val = fmaxf(fmaf(h, sc, sh), 0.0f);
    int cz = coord[v * 3 + 0];
    int cy = coord[v * 3 + 1];
    int cx = coord[v * 3 + 2];
    size_t off = (size_t)u * (DD * HH * WWG) + (size_t)cz * (HH * WWG) + (size_t)cy * WWG + cx;
    atomicAdd(out + off, val);
}

// ---------------- launch -----------------------------------------------------------
extern "C" void kernel_launch(void* const* d_in, const int* in_sizes, int n_in,
                              void* d_out, int out_size) {
    const float* x     = (const float*)d_in[0];
    const int*   coord = (const int*)  d_in[1];
    const float* W1 = (const float*)d_in[2];
    const float* b1 = (const float*)d_in[3];
    const float* g1 = (const float*)d_in[4];
    const float* be1= (const float*)d_in[5];
    const float* W2 = (const float*)d_in[6];
    const float* b2 = (const float*)d_in[7];
    const float* g2 = (const float*)d_in[8];
    const float* be2= (const float*)d_in[9];
    const float* Wd = (const float*)d_in[10];
    const float* bd = (const float*)d_in[11];
    const float* gd = (const float*)d_in[12];
    const float* bed= (const float*)d_in[13];

    int V = in_sizes[1] / 3;
    if (V > VMAX) V = VMAX;
    double invN = 1.0 / ((double)V * PP);

    cudaFuncSetAttribute(k_vfe2, cudaFuncAttributeMaxDynamicSharedMemorySize, SM2_BYTES);

    cudaMemsetAsync(d_out, 0, (size_t)out_size * sizeof(float), 0);
    k_zero_stats<<<32, 256>>>();
    k_stats1<<<592, 256>>>(x, W1, b1, V);
    k_finalize<<<1, 256>>>(g1, be1, 0, C1, invN);
    k_vfe1<<<V, 128>>>(x, W1, b1, W2, b2, V);
    k_finalize<<<1, 256>>>(g2, be2, C1, C2, invN);
    k_vfe2<<<GRID2, T2, SM2_BYTES>>>((const float4*)Wd, bd, V);
    k_finalize<<<1, 256>>>(gd, bed, C1 + C2, C3, invN);
    k_scatter<<<V, 128>>>(coord, (float*)d_out, V);
}

// round 7
// speedup vs baseline: 1.1280x; 1.1280x over previous
#include <cuda_runtime.h>

#define PP    35
#define CIN   7
#define C1    16
#define A1C   32
#define C2    64
#define A2C   128
#define C3    128
#define DD    10
#define HH    200
#define WWG   176
#define VMAX  20000
#define NBUCK 64
#define NCH   (C1 + C2 + C3)   // 208
#define NP1   20
#define T2V   512              // vfe2 threads per CTA
#define NGRP  3
#define GT    160              // threads per group
#define GRID2 148
#define NSTREAM (GRID2 * NGRP) // 444

typedef unsigned long long ull;

// ---------------- scratch ---------------------------------------------------------
__device__ float  g_h2[(size_t)VMAX * PP * C2];    // pre-BN h2
__device__ float  g_keep[(size_t)VMAX * PP];
__device__ float  g_max3[(size_t)VMAX * C3];
__device__ float  g_min3[(size_t)VMAX * C3];
__device__ double g_sumB [NBUCK][NCH];
__device__ double g_sqB  [NBUCK][NCH];
__device__ float  g_scale[NCH];
__device__ float  g_shift[NCH];

// ---------------- f32x2 helpers ----------------------------------------------------
__device__ __forceinline__ ull pack2(float lo, float hi) {
    ull r;
    asm("mov.b64 %0, {%1, %2};" : "=l"(r) : "f"(lo), "f"(hi));
    return r;
}
__device__ __forceinline__ float2 unpack2(ull v) {
    float2 r;
    asm("mov.b64 {%0, %1}, %2;" : "=f"(r.x), "=f"(r.y) : "l"(v));
    return r;
}
__device__ __forceinline__ void fma2(ull& d, ull a, ull b) {
    asm("fma.rn.f32x2 %0, %1, %2, %0;" : "+l"(d) : "l"(a), "l"(b));
}

// ---------------- zero stat buckets ------------------------------------------------
__global__ void k_zero_stats() {
    int n = NBUCK * NCH;
    for (int i = blockIdx.x * blockDim.x + threadIdx.x; i < n; i += gridDim.x * blockDim.x) {
        ((double*)g_sumB)[i] = 0.0;
        ((double*)g_sqB)[i]  = 0.0;
    }
}

// ---------------- pass 1: stats of h1 ---------------------------------------------
__global__ void k_stats1(const float* __restrict__ x,
                         const float* __restrict__ W1,
                         const float* __restrict__ b1, int V) {
    int N = V * PP;
    float lsum[C1], lsq[C1];
    #pragma unroll
    for (int u = 0; u < C1; u++) { lsum[u] = 0.f; lsq[u] = 0.f; }
    for (int r = blockIdx.x * blockDim.x + threadIdx.x; r < N; r += gridDim.x * blockDim.x) {
        float xv[CIN];
        #pragma unroll
        for (int c = 0; c < CIN; c++) xv[c] = x[(size_t)r * CIN + c];
        #pragma unroll
        for (int u = 0; u < C1; u++) {
            float h = b1[u];
            #pragma unroll
            for (int c = 0; c < CIN; c++) h = fmaf(xv[c], W1[c * C1 + u], h);
            lsum[u] += h; lsq[u] += h * h;
        }
    }
    __shared__ float ssum[C1], ssq[C1];
    if (threadIdx.x < C1) { ssum[threadIdx.x] = 0.f; ssq[threadIdx.x] = 0.f; }
    __syncthreads();
    #pragma unroll
    for (int u = 0; u < C1; u++) { atomicAdd(&ssum[u], lsum[u]); atomicAdd(&ssq[u], lsq[u]); }
    __syncthreads();
    if (threadIdx.x < C1) {
        int b = blockIdx.x & (NBUCK - 1);
        atomicAdd(&g_sumB[b][threadIdx.x], (double)ssum[threadIdx.x]);
        atomicAdd(&g_sqB [b][threadIdx.x], (double)ssq [threadIdx.x]);
    }
}

// ---------------- finalize BN params -----------------------------------------------
__global__ void k_finalize(const float* __restrict__ g, const float* __restrict__ be,
                           int off, int nc, double invN) {
    int u = threadIdx.x;
    if (u < nc) {
        double s = 0.0, q = 0.0;
        for (int b = 0; b < NBUCK; b++) { s += g_sumB[b][off + u]; q += g_sqB[b][off + u]; }
        double m   = s * invN;
        double var = q * invN - m * m;
        float  sc  = g[u] * rsqrtf((float)var + 1e-5f);
        g_scale[off + u] = sc;
        g_shift[off + u] = (float)((double)be[u] - m * (double)sc);
    }
}

// ---------------- pass 2: BN1+relu, max; HALVED h2 GEMM -> g_h2 -------------------
__global__ void __launch_bounds__(128) k_vfe1(const float* __restrict__ x,
                       const float* __restrict__ W1, const float* __restrict__ b1,
                       const float* __restrict__ W2, const float* __restrict__ b2, int V) {
    int v = blockIdx.x;
    if (v >= V) return;
    int t = threadIdx.x;

    __shared__ float  s_x[PP * CIN];
    __shared__ float  s_keep[PP + 1];
    __shared__ float  s_h1[PP * C1];
    __shared__ float  s_m1[C1];
    __shared__ float  s_C[C2];
    __shared__ float2 s_a1p[C1 * NP1];
    __shared__ float  s_w2[A1C * C2];
    __shared__ float  s_rs[4 * C2], s_rq[4 * C2];

    const float* xb = x + (size_t)v * (PP * CIN);
    for (int i = t; i < PP * CIN; i += 128) s_x[i] = xb[i];
    for (int i = t; i < A1C * C2; i += 128) s_w2[i] = W2[i];
    __syncthreads();

    if (t < PP) {
        float s = 0.f;
        #pragma unroll
        for (int c = 0; c < CIN; c++) s += s_x[t * CIN + c];
        float k = (s != 0.0f) ? 1.0f : 0.0f;
        s_keep[t] = k;
        g_keep[(size_t)v * PP + t] = k;
    }
    __syncthreads();

    for (int i = t; i < PP * C1; i += 128) {
        int p = i >> 4, u = i & 15;
        float h = b1[u];
        #pragma unroll
        for (int c = 0; c < CIN; c++) h = fmaf(s_x[p * CIN + c], W1[c * C1 + u], h);
        h = fmaf(h, g_scale[u], g_shift[u]);
        s_h1[i] = fmaxf(h, 0.0f);
    }
    __syncthreads();

    if (t < C1) {
        float m = s_h1[t];
        #pragma unroll 7
        for (int p = 1; p < PP; p++) m = fmaxf(m, s_h1[p * C1 + t]);
        s_m1[t] = m;
    }
    __syncthreads();

    for (int i = t; i < C1 * NP1; i += 128) {
        int k = i / NP1, pr = i % NP1;
        int p0 = 2 * pr, p1 = p0 + 1;
        float u0 = 0.f, u1 = 0.f;
        if (p0 < PP) u0 = s_h1[p0 * C1 + k] * s_keep[p0];
        if (p1 < PP) u1 = s_h1[p1 * C1 + k] * s_keep[p1];
        s_a1p[i] = make_float2(u0, u1);
    }
    if (t < C2) {
        float c = 0.f;
        #pragma unroll
        for (int k = 0; k < C1; k++) c = fmaf(s_m1[k], s_w2[(C1 + k) * C2 + t], c);
        s_C[t] = c;
    }
    __syncthreads();

    int lane = t & 31, pg = t >> 5;
    int og = lane * 2;
    ull acc[5][2];
    #pragma unroll
    for (int n = 0; n < 5; n++) { acc[n][0] = 0ULL; acc[n][1] = 0ULL; }

    #pragma unroll 4
    for (int k = 0; k < C1; k++) {
        float2 w = *(const float2*)&s_w2[k * C2 + og];
        ull w0 = pack2(w.x, w.x), w1 = pack2(w.y, w.y);
        const ull* ap = (const ull*)&s_a1p[k * NP1 + pg * 5];
        #pragma unroll
        for (int n = 0; n < 5; n++) {
            ull a = ap[n];
            fma2(acc[n][0], a, w0);
            fma2(acc[n][1], a, w1);
        }
    }

    float C0 = s_C[og], C1v = s_C[og + 1];
    float b0 = b2[og],  b1s = b2[og + 1];
    float ls0 = 0.f, lq0 = 0.f, ls1 = 0.f, lq1 = 0.f;
    float* h2g = g_h2 + (size_t)v * (PP * C2);
    #pragma unroll
    for (int n = 0; n < 5; n++) {
        int pr = pg * 5 + n;
        if (pr < 18) {
            int p0 = 2 * pr, p1 = p0 + 1;
            float2 r0 = unpack2(acc[n][0]);
            float2 r1 = unpack2(acc[n][1]);
            float k0 = s_keep[p0];
            float h00 = fmaf(k0, r0.x + C0,  b0);
            float h01 = fmaf(k0, r1.x + C1v, b1s);
            *(float2*)&h2g[p0 * C2 + og] = make_float2(h00, h01);
            ls0 += h00; lq0 += h00 * h00;
            ls1 += h01; lq1 += h01 * h01;
            if (p1 < PP) {
                float k1 = s_keep[p1];
                float h10 = fmaf(k1, r0.y + C0,  b0);
                float h11 = fmaf(k1, r1.y + C1v, b1s);
                *(float2*)&h2g[p1 * C2 + og] = make_float2(h10, h11);
                ls0 += h10; lq0 += h10 * h10;
                ls1 += h11; lq1 += h11 * h11;
            }
        }
    }
    s_rs[pg * C2 + og] = ls0; s_rs[pg * C2 + og + 1] = ls1;
    s_rq[pg * C2 + og] = lq0; s_rq[pg * C2 + og + 1] = lq1;
    __syncthreads();
    if (t < C2) {
        float S = s_rs[t] + s_rs[C2 + t] + s_rs[2 * C2 + t] + s_rs[3 * C2 + t];
        float Q = s_rq[t] + s_rq[C2 + t] + s_rq[2 * C2 + t] + s_rq[3 * C2 + t];
        int b = v & (NBUCK - 1);
        atomicAdd(&g_sumB[b][C1 + t], (double)S);
        atomicAdd(&g_sqB [b][C1 + t], (double)Q);
    }
}

// ---------------- pass 3: 1 CTA/SM, 3 independent 160-thread groups ---------------
// transposed row layout: for output o (ogi=o>>4, j=(o>>1)&7, e=o&1):
//   phys = (j>>1)*32 + ogi*4 + (j&1)*2 + e
#define HB_S  68
#define H3_S  132
// shared (floats): s_wd [128][128] at 0; s_sc 16384; s_sh 16448; groups at 16512
#define F_SC   16384
#define F_SH   16448
#define F_GRP  16512
#define GRPSZ  7700
#define G_HB   0
#define G_H3   2720
#define G_B    7340
#define G_MM   7468
#define G_M2   7596
#define G_KEEP 7660
#define SM2_BYTES ((F_GRP + NGRP * GRPSZ) * 4)

#define GBAR() asm volatile("bar.sync %0, %1;" :: "r"(gi + 1), "r"(GT) : "memory")

__global__ void __launch_bounds__(T2V, 1) k_vfe2(const float4* __restrict__ Wd4,
                                                 const float*  __restrict__ bd, int V) {
    extern __shared__ float sm2[];
    float* s_wd = sm2;
    float* s_sc = sm2 + F_SC;
    float* s_sh = sm2 + F_SH;

    int t = threadIdx.x;

    // ---- one-time staging (all 512 threads) ----
    for (int i = t; i < A2C * 32; i += T2V) {
        int k = i >> 5, c = i & 31;
        float4 wv = Wd4[i];
        float* base = s_wd + k * A2C + (c & 3) * 32 + (c >> 2) * 4;
        *(ull*)(base)     = pack2(wv.x, wv.y);
        *(ull*)(base + 2) = pack2(wv.z, wv.w);
    }
    if (t < C2) { s_sc[t] = g_scale[C1 + t]; s_sh[t] = g_shift[C1 + t]; }
    // zero pad rows (35..39) of each group's s_hb
    for (int i = t; i < NGRP * 5 * HB_S; i += T2V) {
        int g = i / (5 * HB_S), r = i % (5 * HB_S);
        sm2[F_GRP + g * GRPSZ + G_HB + 35 * HB_S + r] = 0.f;
    }
    __syncthreads();

    if (t >= NGRP * GT) return;   // threads 480..511 idle

    int gi = t / GT;              // group 0..2 (warp-uniform: GT=160=5 warps)
    int lt = t - gi * GT;         // 0..159

    float* gb     = sm2 + F_GRP + gi * GRPSZ;
    float* s_hb   = gb + G_HB;
    float* s_h3   = gb + G_H3;
    float* s_B    = gb + G_B;
    float* s_mm   = gb + G_MM;
    float* s_m2   = gb + G_M2;
    float* s_keep = gb + G_KEEP;

    int ogi = lt & 7;
    int pg  = lt >> 3;            // 0..19
    int p0  = 2 * pg, p1 = p0 + 1;

    for (int v = blockIdx.x * NGRP + gi; v < V; v += NSTREAM) {
        // ---- phase 1: keep + h2 load + BN2 + relu -> s_hb ----
        if (lt < 40) s_keep[lt] = (lt < PP) ? g_keep[(size_t)v * PP + lt] : 0.f;
        const float4* h2g4 = (const float4*)(g_h2 + (size_t)v * (PP * C2));
        for (int i = lt; i < (PP * C2) / 4; i += GT) {
            float4 h = h2g4[i];
            int p = i >> 4, c4 = i & 15, u = c4 * 4;
            h.x = fmaxf(fmaf(h.x, s_sc[u],     s_sh[u]),     0.f);
            h.y = fmaxf(fmaf(h.y, s_sc[u + 1], s_sh[u + 1]), 0.f);
            h.z = fmaxf(fmaf(h.z, s_sc[u + 2], s_sh[u + 2]), 0.f);
            h.w = fmaxf(fmaf(h.w, s_sc[u + 3], s_sh[u + 3]), 0.f);
            ((float4*)(s_hb + p * HB_S))[c4] = h;
        }
        GBAR();

        // ---- phase 2: partial column max ----
        if (lt < 128) {
            int ch = lt & 63, half = lt >> 6;
            int pb = half * 18, pe = half ? PP : 18;
            float m = -3.4e38f;
            for (int p = pb; p < pe; p++) m = fmaxf(m, s_hb[p * HB_S + ch]);
            s_mm[half * 64 + ch] = m;
        }
        GBAR();

        if (lt < C2) s_m2[lt] = fmaxf(s_mm[lt], s_mm[64 + lt]);
        GBAR();

        // ---- phase 3: fold keep into s_hb; compute B (phys channel space) ----
        for (int i = lt; i < PP * C2; i += GT) {
            int p = i >> 6, u = i & 63;
            s_hb[p * HB_S + u] *= s_keep[p];
        }
        if (lt < 128) {
            float bsum = 0.f;
            #pragma unroll 8
            for (int k = 0; k < 64; k++)
                bsum = fmaf(s_m2[k], s_wd[(64 + k) * A2C + lt], bsum);
            s_B[lt] = bsum;
        }
        GBAR();

        // ---- phase 4: GEMM (k<64): 16 outputs x 2 points ----
        ull acc0[8], acc1[8];
        #pragma unroll
        for (int j = 0; j < 8; j++) {
            ull b = ((const ull*)bd)[8 * ogi + j];
            acc0[j] = b; acc1[j] = b;
        }
        const float* hb0 = s_hb + p0 * HB_S;
        const float* hb1 = s_hb + p1 * HB_S;

        #pragma unroll 4
        for (int k = 0; k < 64; k++) {
            const ulonglong2* wk = (const ulonglong2*)(s_wd + k * A2C);
            float a0f = hb0[k], a1f = hb1[k];
            ull a0 = pack2(a0f, a0f), a1 = pack2(a1f, a1f);
            #pragma unroll
            for (int q = 0; q < 4; q++) {
                ulonglong2 w = wk[8 * q + ogi];
                fma2(acc0[2 * q],     a0, w.x);
                fma2(acc0[2 * q + 1], a0, w.y);
                fma2(acc1[2 * q],     a1, w.x);
                fma2(acc1[2 * q + 1], a1, w.y);
            }
        }

        // epilogue: + keep*B
        {
            float kp0 = s_keep[p0], kp1 = s_keep[p1];
            ull kpp0 = pack2(kp0, kp0), kpp1 = pack2(kp1, kp1);
            const ulonglong2* sB2 = (const ulonglong2*)s_B;
            #pragma unroll
            for (int q = 0; q < 4; q++) {
                ulonglong2 Bq = sB2[8 * q + ogi];
                fma2(acc0[2 * q],     Bq.x, kpp0);
                fma2(acc0[2 * q + 1], Bq.y, kpp0);
                fma2(acc1[2 * q],     Bq.x, kpp1);
                fma2(acc1[2 * q + 1], Bq.y, kpp1);
            }
        }

        // store h3 tile (phys layout), real points only
        if (p0 < PP) {
            ulonglong2* dst = (ulonglong2*)(s_h3 + p0 * H3_S);
            #pragma unroll
            for (int q = 0; q < 4; q++) {
                ulonglong2 val; val.x = acc0[2 * q]; val.y = acc0[2 * q + 1];
                dst[8 * q + ogi] = val;
            }
        }
        if (p1 < PP) {
            ulonglong2* dst = (ulonglong2*)(s_h3 + p1 * H3_S);
            #pragma unroll
            for (int q = 0; q < 4; q++) {
                ulonglong2 val; val.x = acc1[2 * q]; val.y = acc1[2 * q + 1];
                dst[8 * q + ogi] = val;
            }
        }
        GBAR();

        // ---- phase 5: stats over 35 points (phys col lt -> true channel o) ----
        if (lt < C3) {
            float S = 0.f, Q = 0.f, MX = -3.4e38f, MN = 3.4e38f;
            #pragma unroll 7
            for (int p = 0; p < PP; p++) {
                float val = s_h3[p * H3_S + lt];
                S += val; Q = fmaf(val, val, Q);
                MX = fmaxf(MX, val); MN = fminf(MN, val);
            }
            int r = lt & 31;
            int o = (r >> 2) * 16 + (lt >> 5) * 4 + (r & 3);
            g_max3[(size_t)v * C3 + o] = MX;
            g_min3[(size_t)v * C3 + o] = MN;
            int b = v & (NBUCK - 1);
            atomicAdd(&g_sumB[b][C1 + C2 + o], (double)S);
            atomicAdd(&g_sqB [b][C1 + C2 + o], (double)Q);
        }
        GBAR();
    }
}

// ---------------- pass 4: BN3 + relu + max (via max/min) + scatter-add ------------
__global__ void k_scatter(const int* __restrict__ coord, float* __restrict__ out, int V) {
    int v = blockIdx.x;
    if (v >= V) return;
    int u = threadIdx.x;
    float sc = g_scale[C1 + C2 + u];
    float sh = g_shift[C1 + C2 + u];
    float h  = (sc >= 0.0f) ? g_max3[(size_t)v * C3 + u] : g_min3[(size_t)v * C3 + u];
    float val = fmaxf(fmaf(h, sc, sh), 0.0f);
    int cz = coord[v * 3 + 0];
    int cy = coord[v * 3 + 1];
    int cx = coord[v * 3 + 2];
    size_t off = (size_t)u * (DD * HH * WWG) + (size_t)cz * (HH * WWG) + (size_t)cy * WWG + cx;
    atomicAdd(out + off, val);
}

// ---------------- launch -----------------------------------------------------------
extern "C" void kernel_launch(void* const* d_in, const int* in_sizes, int n_in,
                              void* d_out, int out_size) {
    const float* x     = (const float*)d_in[0];
    const int*   coord = (const int*)  d_in[1];
    const float* W1 = (const float*)d_in[2];
    const float* b1 = (const float*)d_in[3];
    const float* g1 = (const float*)d_in[4];
    const float* be1= (const float*)d_in[5];
    const float* W2 = (const float*)d_in[6];
    const float* b2 = (const float*)d_in[7];
    const float* g2 = (const float*)d_in[8];
    const float* be2= (const float*)d_in[9];
    const float* Wd = (const float*)d_in[10];
    const float* bd = (const float*)d_in[11];
    const float* gd = (const float*)d_in[12];
    const float* bed= (const float*)d_in[13];

    int V = in_sizes[1] / 3;
    if (V > VMAX) V = VMAX;
    double invN = 1.0 / ((double)V * PP);

    cudaFuncSetAttribute(k_vfe2, cudaFuncAttributeMaxDynamicSharedMemorySize, SM2_BYTES);

    cudaMemsetAsync(d_out, 0, (size_t)out_size * sizeof(float), 0);
    k_zero_stats<<<32, 256>>>();
    k_stats1<<<592, 256>>>(x, W1, b1, V);
    k_finalize<<<1, 256>>>(g1, be1, 0, C1, invN);
    k_vfe1<<<V, 128>>>(x, W1, b1, W2, b2, V);
    k_finalize<<<1, 256>>>(g2, be2, C1, C2, invN);
    k_vfe2<<<GRID2, T2V, SM2_BYTES>>>((const float4*)Wd, bd, V);
    k_finalize<<<1, 256>>>(gd, bed, C1 + C2, C3, invN);
    k_scatter<<<V, 128>>>(coord, (float*)d_out, V);
}

// round 9
// speedup vs baseline: 1.2458x; 1.1044x over previous
#include <cuda_runtime.h>

#define PP    35
#define CIN   7
#define C1    16
#define A1C   32
#define C2    64
#define A2C   128
#define C3    128
#define DD    10
#define HH    200
#define WWG   176
#define VMAX  20000
#define NBUCK 64
#define NCH   (C1 + C2 + C3)   // 208
#define NP1   20
#define NGRP  7
#define GT    64               // threads per group (2 warps)
#define T2V   (NGRP * GT)      // 448
#define GRID2 148
#define NSTREAM (GRID2 * NGRP) // 1036

typedef unsigned long long ull;

// ---------------- scratch ---------------------------------------------------------
__device__ float  g_h2[(size_t)VMAX * PP * C2];    // pre-BN h2
__device__ float  g_keep[(size_t)VMAX * PP];
__device__ float  g_max3[(size_t)VMAX * C3];
__device__ float  g_min3[(size_t)VMAX * C3];
__device__ double g_sumB [NBUCK][NCH];
__device__ double g_sqB  [NBUCK][NCH];
__device__ float  g_scale[NCH];
__device__ float  g_shift[NCH];

// ---------------- f32x2 helpers ----------------------------------------------------
__device__ __forceinline__ ull pack2(float lo, float hi) {
    ull r;
    asm("mov.b64 %0, {%1, %2};" : "=l"(r) : "f"(lo), "f"(hi));
    return r;
}
__device__ __forceinline__ float2 unpack2(ull v) {
    float2 r;
    asm("mov.b64 {%0, %1}, %2;" : "=f"(r.x), "=f"(r.y) : "l"(v));
    return r;
}
__device__ __forceinline__ void fma2(ull& d, ull a, ull b) {
    asm("fma.rn.f32x2 %0, %1, %2, %0;" : "+l"(d) : "l"(a), "l"(b));
}
__device__ __forceinline__ void add2(ull& d, ull a) {
    asm("add.rn.f32x2 %0, %0, %1;" : "+l"(d) : "l"(a));
}

// ---------------- zero stat buckets ------------------------------------------------
__global__ void k_zero_stats() {
    int n = NBUCK * NCH;
    for (int i = blockIdx.x * blockDim.x + threadIdx.x; i < n; i += gridDim.x * blockDim.x) {
        ((double*)g_sumB)[i] = 0.0;
        ((double*)g_sqB)[i]  = 0.0;
    }
}

// ---------------- pass 1: stats of h1 ---------------------------------------------
__global__ void k_stats1(const float* __restrict__ x,
                         const float* __restrict__ W1,
                         const float* __restrict__ b1, int V) {
    int N = V * PP;
    float lsum[C1], lsq[C1];
    #pragma unroll
    for (int u = 0; u < C1; u++) { lsum[u] = 0.f; lsq[u] = 0.f; }
    for (int r = blockIdx.x * blockDim.x + threadIdx.x; r < N; r += gridDim.x * blockDim.x) {
        float xv[CIN];
        #pragma unroll
        for (int c = 0; c < CIN; c++) xv[c] = x[(size_t)r * CIN + c];
        #pragma unroll
        for (int u = 0; u < C1; u++) {
            float h = b1[u];
            #pragma unroll
            for (int c = 0; c < CIN; c++) h = fmaf(xv[c], W1[c * C1 + u], h);
            lsum[u] += h; lsq[u] += h * h;
        }
    }
    __shared__ float ssum[C1], ssq[C1];
    if (threadIdx.x < C1) { ssum[threadIdx.x] = 0.f; ssq[threadIdx.x] = 0.f; }
    __syncthreads();
    #pragma unroll
    for (int u = 0; u < C1; u++) { atomicAdd(&ssum[u], lsum[u]); atomicAdd(&ssq[u], lsq[u]); }
    __syncthreads();
    if (threadIdx.x < C1) {
        int b = blockIdx.x & (NBUCK - 1);
        atomicAdd(&g_sumB[b][threadIdx.x], (double)ssum[threadIdx.x]);
        atomicAdd(&g_sqB [b][threadIdx.x], (double)ssq [threadIdx.x]);
    }
}

// ---------------- finalize BN params -----------------------------------------------
__global__ void k_finalize(const float* __restrict__ g, const float* __restrict__ be,
                           int off, int nc, double invN) {
    int u = threadIdx.x;
    if (u < nc) {
        double s = 0.0, q = 0.0;
        for (int b = 0; b < NBUCK; b++) { s += g_sumB[b][off + u]; q += g_sqB[b][off + u]; }
        double m   = s * invN;
        double var = q * invN - m * m;
        float  sc  = g[u] * rsqrtf((float)var + 1e-5f);
        g_scale[off + u] = sc;
        g_shift[off + u] = (float)((double)be[u] - m * (double)sc);
    }
}

// ---------------- pass 2: BN1+relu, max; HALVED h2 GEMM -> g_h2 -------------------
__global__ void __launch_bounds__(128) k_vfe1(const float* __restrict__ x,
                       const float* __restrict__ W1, const float* __restrict__ b1,
                       const float* __restrict__ W2, const float* __restrict__ b2, int V) {
    int v = blockIdx.x;
    if (v >= V) return;
    int t = threadIdx.x;

    __shared__ float  s_x[PP * CIN];
    __shared__ float  s_keep[PP + 1];
    __shared__ float  s_h1[PP * C1];
    __shared__ float  s_m1[C1];
    __shared__ float  s_C[C2];
    __shared__ float2 s_a1p[C1 * NP1];
    __shared__ float  s_w2[A1C * C2];
    __shared__ float  s_rs[4 * C2], s_rq[4 * C2];

    const float* xb = x + (size_t)v * (PP * CIN);
    for (int i = t; i < PP * CIN; i += 128) s_x[i] = xb[i];
    for (int i = t; i < A1C * C2; i += 128) s_w2[i] = W2[i];
    __syncthreads();

    if (t < PP) {
        float s = 0.f;
        #pragma unroll
        for (int c = 0; c < CIN; c++) s += s_x[t * CIN + c];
        float k = (s != 0.0f) ? 1.0f : 0.0f;
        s_keep[t] = k;
        g_keep[(size_t)v * PP + t] = k;
    }
    __syncthreads();

    for (int i = t; i < PP * C1; i += 128) {
        int p = i >> 4, u = i & 15;
        float h = b1[u];
        #pragma unroll
        for (int c = 0; c < CIN; c++) h = fmaf(s_x[p * CIN + c], W1[c * C1 + u], h);
        h = fmaf(h, g_scale[u], g_shift[u]);
        s_h1[i] = fmaxf(h, 0.0f);
    }
    __syncthreads();

    if (t < C1) {
        float m = s_h1[t];
        #pragma unroll 7
        for (int p = 1; p < PP; p++) m = fmaxf(m, s_h1[p * C1 + t]);
        s_m1[t] = m;
    }
    __syncthreads();

    for (int i = t; i < C1 * NP1; i += 128) {
        int k = i / NP1, pr = i % NP1;
        int p0 = 2 * pr, p1 = p0 + 1;
        float u0 = 0.f, u1 = 0.f;
        if (p0 < PP) u0 = s_h1[p0 * C1 + k] * s_keep[p0];
        if (p1 < PP) u1 = s_h1[p1 * C1 + k] * s_keep[p1];
        s_a1p[i] = make_float2(u0, u1);
    }
    if (t < C2) {
        float c = 0.f;
        #pragma unroll
        for (int k = 0; k < C1; k++) c = fmaf(s_m1[k], s_w2[(C1 + k) * C2 + t], c);
        s_C[t] = c;
    }
    __syncthreads();

    int lane = t & 31, pg = t >> 5;
    int og = lane * 2;
    ull acc[5][2];
    #pragma unroll
    for (int n = 0; n < 5; n++) { acc[n][0] = 0ULL; acc[n][1] = 0ULL; }

    #pragma unroll 4
    for (int k = 0; k < C1; k++) {
        float2 w = *(const float2*)&s_w2[k * C2 + og];
        ull w0 = pack2(w.x, w.x), w1 = pack2(w.y, w.y);
        const ull* ap = (const ull*)&s_a1p[k * NP1 + pg * 5];
        #pragma unroll
        for (int n = 0; n < 5; n++) {
            ull a = ap[n];
            fma2(acc[n][0], a, w0);
            fma2(acc[n][1], a, w1);
        }
    }

    float C0 = s_C[og], C1v = s_C[og + 1];
    float b0 = b2[og],  b1s = b2[og + 1];
    float ls0 = 0.f, lq0 = 0.f, ls1 = 0.f, lq1 = 0.f;
    float* h2g = g_h2 + (size_t)v * (PP * C2);
    #pragma unroll
    for (int n = 0; n < 5; n++) {
        int pr = pg * 5 + n;
        if (pr < 18) {
            int p0 = 2 * pr, p1 = p0 + 1;
            float2 r0 = unpack2(acc[n][0]);
            float2 r1 = unpack2(acc[n][1]);
            float k0 = s_keep[p0];
            float h00 = fmaf(k0, r0.x + C0,  b0);
            float h01 = fmaf(k0, r1.x + C1v, b1s);
            *(float2*)&h2g[p0 * C2 + og] = make_float2(h00, h01);
            ls0 += h00; lq0 += h00 * h00;
            ls1 += h01; lq1 += h01 * h01;
            if (p1 < PP) {
                float k1 = s_keep[p1];
                float h10 = fmaf(k1, r0.y + C0,  b0);
                float h11 = fmaf(k1, r1.y + C1v, b1s);
                *(float2*)&h2g[p1 * C2 + og] = make_float2(h10, h11);
                ls0 += h10; lq0 += h10 * h10;
                ls1 += h11; lq1 += h11 * h11;
            }
        }
    }
    s_rs[pg * C2 + og] = ls0; s_rs[pg * C2 + og + 1] = ls1;
    s_rq[pg * C2 + og] = lq0; s_rq[pg * C2 + og + 1] = lq1;
    __syncthreads();
    if (t < C2) {
        float S = s_rs[t] + s_rs[C2 + t] + s_rs[2 * C2 + t] + s_rs[3 * C2 + t];
        float Q = s_rq[t] + s_rq[C2 + t] + s_rq[2 * C2 + t] + s_rq[3 * C2 + t];
        int b = v & (NBUCK - 1);
        atomicAdd(&g_sumB[b][C1 + t], (double)S);
        atomicAdd(&g_sqB [b][C1 + t], (double)Q);
    }
}

// ---------------- pass 3: 7 groups x 64 threads; fused prep; 5-point GEMM ---------
// phys channel map: true o = 16*ogi + 4q + r  <->  phys = 32q + 4*ogi + r
#define HB_S  68           // 272 B/row: float4-aligned; slot banks 4*slot (conflict-free)
#define H3_S  132
#define G_BUF 0            // 4620 floats: hb [40][68]=2720 then h3 [35][132]=4620 (shared)
#define G_B   4620         // 128
#define G_MM  4748         // 512: [4 wgrp][16 cgrp][8]
#define G_M2  5260         // 64
#define GRPSZ 5328
#define F_SC  16384
#define F_SH  16448
#define F_GRP 16512
#define SM2_BYTES ((F_GRP + NGRP * GRPSZ) * 4)

#define GBAR() asm volatile("bar.sync %0, %1;" :: "r"(gi + 1), "r"(GT) : "memory")

__global__ void __launch_bounds__(T2V, 1) k_vfe2(const float4* __restrict__ Wd4,
                                                 const float*  __restrict__ bd, int V) {
    extern __shared__ float sm2[];
    float* s_wd = sm2;                 // [128][128] phys-permuted
    float* s_sc = sm2 + F_SC;
    float* s_sh = sm2 + F_SH;

    int t = threadIdx.x;

    // ---- one-time staging ----
    for (int i = t; i < A2C * 32; i += T2V) {
        int k = i >> 5, c = i & 31;
        float4 wv = Wd4[i];
        *(float4*)(s_wd + k * A2C + (c & 3) * 32 + (c >> 2) * 4) = wv;
    }
    if (t < C2) { s_sc[t] = g_scale[C1 + t]; s_sh[t] = g_shift[C1 + t]; }
    __syncthreads();

    int gi = t / GT;                   // group 0..6 (64 = 2 warps, warp-uniform)
    int lt = t - gi * GT;

    float* buf  = sm2 + F_GRP + gi * GRPSZ + G_BUF;
    float* s_B  = sm2 + F_GRP + gi * GRPSZ + G_B;
    float* s_mm = sm2 + F_GRP + gi * GRPSZ + G_MM;
    float* s_m2 = sm2 + F_GRP + gi * GRPSZ + G_M2;

    int ogi  = lt & 7;                 // 16 outputs: o in [16*ogi, 16*ogi+16)
    int slot = lt >> 3;                // 0..7 -> rows slot+8j, j=0..4

    for (int v = blockIdx.x * NGRP + gi; v < V; v += NSTREAM) {
        const float* keepg = g_keep + (size_t)v * PP;

        // ---- phase 1: load h2 + BN2 + relu + keep-fold -> hb; raw min/max ----
        {
            float rmx[4], rmn[4];
            #pragma unroll
            for (int q = 0; q < 4; q++) { rmx[q] = -3.4e38f; rmn[q] = 3.4e38f; }
            const float4* h2g4 = (const float4*)(g_h2 + (size_t)v * (PP * C2));
            int c4 = (lt & 15) * 4;
            float4 scv = *(const float4*)(s_sc + c4);
            float4 shv = *(const float4*)(s_sh + c4);
            for (int i = lt; i < (PP * C2) / 4; i += GT) {
                float4 h = h2g4[i];
                int p = i >> 4;
                float kp = keepg[p];
                rmx[0] = fmaxf(rmx[0], h.x); rmn[0] = fminf(rmn[0], h.x);
                rmx[1] = fmaxf(rmx[1], h.y); rmn[1] = fminf(rmn[1], h.y);
                rmx[2] = fmaxf(rmx[2], h.z); rmn[2] = fminf(rmn[2], h.z);
                rmx[3] = fmaxf(rmx[3], h.w); rmn[3] = fminf(rmn[3], h.w);
                float4 o;
                o.x = fmaxf(fmaf(h.x, scv.x, shv.x), 0.f) * kp;
                o.y = fmaxf(fmaf(h.y, scv.y, shv.y), 0.f) * kp;
                o.z = fmaxf(fmaf(h.z, scv.z, shv.z), 0.f) * kp;
                o.w = fmaxf(fmaf(h.w, scv.w, shv.w), 0.f) * kp;
                *(float4*)(buf + p * HB_S + c4) = o;
            }
            // zero pad rows 35..39 of hb (clobbered by last voxel's h3)
            for (int j = lt; j < 5 * HB_S; j += GT) buf[35 * HB_S + j] = 0.f;
            float* mm = s_mm + (lt >> 4) * 128 + (lt & 15) * 8;
            #pragma unroll
            for (int q = 0; q < 4; q++) { mm[q] = rmx[q]; mm[4 + q] = rmn[q]; }
        }
        GBAR();

        // ---- phase 2: finalize m2 (max over p of relu(bn(h2)), unmasked) ----
        if (lt < C2) {
            int cg = lt >> 2, r = lt & 3;
            float MX = -3.4e38f, MN = 3.4e38f;
            #pragma unroll
            for (int w = 0; w < 4; w++) {
                MX = fmaxf(MX, s_mm[w * 128 + cg * 8 + r]);
                MN = fminf(MN, s_mm[w * 128 + cg * 8 + 4 + r]);
            }
            float sc = s_sc[lt];
            float sel = (sc >= 0.f) ? MX : MN;
            s_m2[lt] = fmaxf(fmaf(sel, sc, s_sh[lt]), 0.f);
        }
        GBAR();

        // ---- phase 3: B vector (phys pair per thread) then GEMM ----
        {
            ull b = 0ULL;
            #pragma unroll 8
            for (int k = 0; k < 64; k++) {
                float m = s_m2[k];
                ull w = *(const ull*)(s_wd + (64 + k) * A2C + 2 * lt);
                fma2(b, pack2(m, m), w);
            }
            *(ull*)(s_B + 2 * lt) = b;
        }

        ull acc[5][8];
        #pragma unroll
        for (int j = 0; j < 5; j++)
            #pragma unroll
            for (int jj = 0; jj < 8; jj++) acc[j][jj] = 0ULL;

        const float* hbs = buf + slot * HB_S;
        #pragma unroll 2
        for (int k = 0; k < 64; k++) {
            const ulonglong2* wk = (const ulonglong2*)(s_wd + k * A2C);
            ulonglong2 w0 = wk[ogi], w1 = wk[8 + ogi];
            ulonglong2 w2 = wk[16 + ogi], w3 = wk[24 + ogi];
            #pragma unroll
            for (int j = 0; j < 5; j++) {
                float a = hbs[j * 8 * HB_S + k];
                ull ap = pack2(a, a);
                fma2(acc[j][0], ap, w0.x); fma2(acc[j][1], ap, w0.y);
                fma2(acc[j][2], ap, w1.x); fma2(acc[j][3], ap, w1.y);
                fma2(acc[j][4], ap, w2.x); fma2(acc[j][5], ap, w2.y);
                fma2(acc[j][6], ap, w3.x); fma2(acc[j][7], ap, w3.y);
            }
        }
        GBAR();   // all hb reads + B writes complete

        // ---- phase 4: epilogue (+keep*B +bd) and h3 store (rows < 35) ----
        {
            ulonglong2 Bq[4], bdq[4];
            #pragma unroll
            for (int q = 0; q < 4; q++) {
                Bq[q] = *(const ulonglong2*)(s_B + q * 32 + ogi * 4);
                ull lo = ((const ull*)bd)[8 * ogi + 2 * q];
                ull hi = ((const ull*)bd)[8 * ogi + 2 * q + 1];
                bdq[q].x = lo; bdq[q].y = hi;
            }
            #pragma unroll
            for (int j = 0; j < 5; j++) {
                int p = slot + 8 * j;
                if (p < PP) {
                    float kp = keepg[p];
                    ull kpp = pack2(kp, kp);
                    ulonglong2* dst = (ulonglong2*)(buf + p * H3_S + ogi * 4);
                    #pragma unroll
                    for (int q = 0; q < 4; q++) {
                        fma2(acc[j][2 * q],     Bq[q].x, kpp);
                        fma2(acc[j][2 * q + 1], Bq[q].y, kpp);
                        add2(acc[j][2 * q],     bdq[q].x);
                        add2(acc[j][2 * q + 1], bdq[q].y);
                        ulonglong2 val; val.x = acc[j][2 * q]; val.y = acc[j][2 * q + 1];
                        dst[q * 8] = val;
                    }
                }
            }
        }
        GBAR();

        // ---- phase 5: stats over 35 points; 2 phys cols per thread ----
        #pragma unroll
        for (int h = 0; h < 2; h++) {
            int c = lt + h * 64;       // phys column
            float S = 0.f, Q = 0.f, MX = -3.4e38f, MN = 3.4e38f;
            #pragma unroll 7
            for (int p = 0; p < PP; p++) {
                float val = buf[p * H3_S + c];
                S += val; Q = fmaf(val, val, Q);
                MX = fmaxf(MX, val); MN = fminf(MN, val);
            }
            int rem = c & 31;
            int o = (rem >> 2) * 16 + (c >> 5) * 4 + (rem & 3);
            g_max3[(size_t)v * C3 + o] = MX;
            g_min3[(size_t)v * C3 + o] = MN;
            int b = v & (NBUCK - 1);
            atomicAdd(&g_sumB[b][C1 + C2 + o], (double)S);
            atomicAdd(&g_sqB [b][C1 + C2 + o], (double)Q);
        }
        GBAR();
    }
}

// ---------------- pass 4: BN3 + relu + max (via max/min) + scatter-add ------------
__global__ void k_scatter(const int* __restrict__ coord, float* __restrict__ out, int V) {
    int v = blockIdx.x;
    if (v >= V) return;
    int u = threadIdx.x;
    float sc = g_scale[C1 + C2 + u];
    float sh = g_shift[C1 + C2 + u];
    float h  = (sc >= 0.0f) ? g_max3[(size_t)v * C3 + u] : g_min3[(size_t)v * C3 + u];
    float val = fmaxf(fmaf(h, sc, sh), 0.0f);
    int cz = coord[v * 3 + 0];
    int cy = coord[v * 3 + 1];
    int cx = coord[v * 3 + 2];
    size_t off = (size_t)u * (DD * HH * WWG) + (size_t)cz * (HH * WWG) + (size_t)cy * WWG + cx;
    atomicAdd(out + off, val);
}

// ---------------- launch -----------------------------------------------------------
extern "C" void kernel_launch(void* const* d_in, const int* in_sizes, int n_in,
                              void* d_out, int out_size) {
    const float* x     = (const float*)d_in[0];
    const int*   coord = (const int*)  d_in[1];
    const float* W1 = (const float*)d_in[2];
    const float* b1 = (const float*)d_in[3];
    const float* g1 = (const float*)d_in[4];
    const float* be1= (const float*)d_in[5];
    const float* W2 = (const float*)d_in[6];
    const float* b2 = (const float*)d_in[7];
    const float* g2 = (const float*)d_in[8];
    const float* be2= (const float*)d_in[9];
    const float* Wd = (const float*)d_in[10];
    const float* bd = (const float*)d_in[11];
    const float* gd = (const float*)d_in[12];
    const float* bed= (const float*)d_in[13];

    int V = in_sizes[1] / 3;
    if (V > VMAX) V = VMAX;
    double invN = 1.0 / ((double)V * PP);

    cudaFuncSetAttribute(k_vfe2, cudaFuncAttributeMaxDynamicSharedMemorySize, SM2_BYTES);

    cudaMemsetAsync(d_out, 0, (size_t)out_size * sizeof(float), 0);
    k_zero_stats<<<32, 256>>>();
    k_stats1<<<592, 256>>>(x, W1, b1, V);
    k_finalize<<<1, 256>>>(g1, be1, 0, C1, invN);
    k_vfe1<<<V, 128>>>(x, W1, b1, W2, b2, V);
    k_finalize<<<1, 256>>>(g2, be2, C1, C2, invN);
    k_vfe2<<<GRID2, T2V, SM2_BYTES>>>((const float4*)Wd, bd, V);
    k_finalize<<<1, 256>>>(gd, bed, C1 + C2, C3, invN);
    k_scatter<<<V, 128>>>(coord, (float*)d_out, V);
}

// round 10
// speedup vs baseline: 1.3339x; 1.0707x over previous
#include <cuda_runtime.h>

#define PP    35
#define CIN   7
#define C1    16
#define A1C   32
#define C2    64
#define A2C   128
#define C3    128
#define DD    10
#define HH    200
#define WWG   176
#define VMAX  20000
#define NBUCK 64
#define NCH   (C1 + C2 + C3)   // 208
#define NP1   20
#define NGRP  8
#define GT    64               // threads per group (2 warps)
#define T2V   (NGRP * GT)      // 512
#define GRID2 148
#define NSTREAM (GRID2 * NGRP) // 1184

typedef unsigned long long ull;

// ---------------- scratch ---------------------------------------------------------
__device__ float  g_h2[(size_t)VMAX * PP * C2];    // pre-BN h2
__device__ float  g_keep[(size_t)VMAX * PP];
__device__ float  g_max3[(size_t)VMAX * C3];
__device__ float  g_min3[(size_t)VMAX * C3];
__device__ double g_sumB [NBUCK][NCH];
__device__ double g_sqB  [NBUCK][NCH];
__device__ float  g_scale[NCH];
__device__ float  g_shift[NCH];

// ---------------- f32x2 helpers ----------------------------------------------------
__device__ __forceinline__ ull pack2(float lo, float hi) {
    ull r;
    asm("mov.b64 %0, {%1, %2};" : "=l"(r) : "f"(lo), "f"(hi));
    return r;
}
__device__ __forceinline__ float2 unpack2(ull v) {
    float2 r;
    asm("mov.b64 {%0, %1}, %2;" : "=f"(r.x), "=f"(r.y) : "l"(v));
    return r;
}
__device__ __forceinline__ void fma2(ull& d, ull a, ull b) {
    asm("fma.rn.f32x2 %0, %1, %2, %0;" : "+l"(d) : "l"(a), "l"(b));
}
__device__ __forceinline__ void add2(ull& d, ull a) {
    asm("add.rn.f32x2 %0, %0, %1;" : "+l"(d) : "l"(a));
}

// ---------------- zero stat buckets ------------------------------------------------
__global__ void k_zero_stats() {
    int n = NBUCK * NCH;
    for (int i = blockIdx.x * blockDim.x + threadIdx.x; i < n; i += gridDim.x * blockDim.x) {
        ((double*)g_sumB)[i] = 0.0;
        ((double*)g_sqB)[i]  = 0.0;
    }
}

// ---------------- pass 1: stats of h1 ---------------------------------------------
__global__ void k_stats1(const float* __restrict__ x,
                         const float* __restrict__ W1,
                         const float* __restrict__ b1, int V) {
    int N = V * PP;
    float lsum[C1], lsq[C1];
    #pragma unroll
    for (int u = 0; u < C1; u++) { lsum[u] = 0.f; lsq[u] = 0.f; }
    for (int r = blockIdx.x * blockDim.x + threadIdx.x; r < N; r += gridDim.x * blockDim.x) {
        float xv[CIN];
        #pragma unroll
        for (int c = 0; c < CIN; c++) xv[c] = x[(size_t)r * CIN + c];
        #pragma unroll
        for (int u = 0; u < C1; u++) {
            float h = b1[u];
            #pragma unroll
            for (int c = 0; c < CIN; c++) h = fmaf(xv[c], W1[c * C1 + u], h);
            lsum[u] += h; lsq[u] += h * h;
        }
    }
    __shared__ float ssum[C1], ssq[C1];
    if (threadIdx.x < C1) { ssum[threadIdx.x] = 0.f; ssq[threadIdx.x] = 0.f; }
    __syncthreads();
    #pragma unroll
    for (int u = 0; u < C1; u++) { atomicAdd(&ssum[u], lsum[u]); atomicAdd(&ssq[u], lsq[u]); }
    __syncthreads();
    if (threadIdx.x < C1) {
        int b = blockIdx.x & (NBUCK - 1);
        atomicAdd(&g_sumB[b][threadIdx.x], (double)ssum[threadIdx.x]);
        atomicAdd(&g_sqB [b][threadIdx.x], (double)ssq [threadIdx.x]);
    }
}

// ---------------- finalize BN params -----------------------------------------------
__global__ void k_finalize(const float* __restrict__ g, const float* __restrict__ be,
                           int off, int nc, double invN) {
    int u = threadIdx.x;
    if (u < nc) {
        double s = 0.0, q = 0.0;
        for (int b = 0; b < NBUCK; b++) { s += g_sumB[b][off + u]; q += g_sqB[b][off + u]; }
        double m   = s * invN;
        double var = q * invN - m * m;
        float  sc  = g[u] * rsqrtf((float)var + 1e-5f);
        g_scale[off + u] = sc;
        g_shift[off + u] = (float)((double)be[u] - m * (double)sc);
    }
}

// ---------------- pass 2: BN1+relu, max; HALVED h2 GEMM -> g_h2 -------------------
__global__ void __launch_bounds__(128) k_vfe1(const float* __restrict__ x,
                       const float* __restrict__ W1, const float* __restrict__ b1,
                       const float* __restrict__ W2, const float* __restrict__ b2, int V) {
    int v = blockIdx.x;
    if (v >= V) return;
    int t = threadIdx.x;

    __shared__ float  s_x[PP * CIN];
    __shared__ float  s_keep[PP + 1];
    __shared__ float  s_h1[PP * C1];
    __shared__ float  s_m1[C1];
    __shared__ float  s_C[C2];
    __shared__ float2 s_a1p[C1 * NP1];
    __shared__ float  s_w2[A1C * C2];
    __shared__ float  s_rs[4 * C2], s_rq[4 * C2];

    const float* xb = x + (size_t)v * (PP * CIN);
    for (int i = t; i < PP * CIN; i += 128) s_x[i] = xb[i];
    for (int i = t; i < A1C * C2; i += 128) s_w2[i] = W2[i];
    __syncthreads();

    if (t < PP) {
        float s = 0.f;
        #pragma unroll
        for (int c = 0; c < CIN; c++) s += s_x[t * CIN + c];
        float k = (s != 0.0f) ? 1.0f : 0.0f;
        s_keep[t] = k;
        g_keep[(size_t)v * PP + t] = k;
    }
    __syncthreads();

    for (int i = t; i < PP * C1; i += 128) {
        int p = i >> 4, u = i & 15;
        float h = b1[u];
        #pragma unroll
        for (int c = 0; c < CIN; c++) h = fmaf(s_x[p * CIN + c], W1[c * C1 + u], h);
        h = fmaf(h, g_scale[u], g_shift[u]);
        s_h1[i] = fmaxf(h, 0.0f);
    }
    __syncthreads();

    if (t < C1) {
        float m = s_h1[t];
        #pragma unroll 7
        for (int p = 1; p < PP; p++) m = fmaxf(m, s_h1[p * C1 + t]);
        s_m1[t] = m;
    }
    __syncthreads();

    for (int i = t; i < C1 * NP1; i += 128) {
        int k = i / NP1, pr = i % NP1;
        int p0 = 2 * pr, p1 = p0 + 1;
        float u0 = 0.f, u1 = 0.f;
        if (p0 < PP) u0 = s_h1[p0 * C1 + k] * s_keep[p0];
        if (p1 < PP) u1 = s_h1[p1 * C1 + k] * s_keep[p1];
        s_a1p[i] = make_float2(u0, u1);
    }
    if (t < C2) {
        float c = 0.f;
        #pragma unroll
        for (int k = 0; k < C1; k++) c = fmaf(s_m1[k], s_w2[(C1 + k) * C2 + t], c);
        s_C[t] = c;
    }
    __syncthreads();

    int lane = t & 31, pg = t >> 5;
    int og = lane * 2;
    ull acc[5][2];
    #pragma unroll
    for (int n = 0; n < 5; n++) { acc[n][0] = 0ULL; acc[n][1] = 0ULL; }

    #pragma unroll 4
    for (int k = 0; k < C1; k++) {
        float2 w = *(const float2*)&s_w2[k * C2 + og];
        ull w0 = pack2(w.x, w.x), w1 = pack2(w.y, w.y);
        const ull* ap = (const ull*)&s_a1p[k * NP1 + pg * 5];
        #pragma unroll
        for (int n = 0; n < 5; n++) {
            ull a = ap[n];
            fma2(acc[n][0], a, w0);
            fma2(acc[n][1], a, w1);
        }
    }

    float C0 = s_C[og], C1v = s_C[og + 1];
    float b0 = b2[og],  b1s = b2[og + 1];
    float ls0 = 0.f, lq0 = 0.f, ls1 = 0.f, lq1 = 0.f;
    float* h2g = g_h2 + (size_t)v * (PP * C2);
    #pragma unroll
    for (int n = 0; n < 5; n++) {
        int pr = pg * 5 + n;
        if (pr < 18) {
            int p0 = 2 * pr, p1 = p0 + 1;
            float2 r0 = unpack2(acc[n][0]);
            float2 r1 = unpack2(acc[n][1]);
            float k0 = s_keep[p0];
            float h00 = fmaf(k0, r0.x + C0,  b0);
            float h01 = fmaf(k0, r1.x + C1v, b1s);
            *(float2*)&h2g[p0 * C2 + og] = make_float2(h00, h01);
            ls0 += h00; lq0 += h00 * h00;
            ls1 += h01; lq1 += h01 * h01;
            if (p1 < PP) {
                float k1 = s_keep[p1];
                float h10 = fmaf(k1, r0.y + C0,  b0);
                float h11 = fmaf(k1, r1.y + C1v, b1s);
                *(float2*)&h2g[p1 * C2 + og] = make_float2(h10, h11);
                ls0 += h10; lq0 += h10 * h10;
                ls1 += h11; lq1 += h11 * h11;
            }
        }
    }
    s_rs[pg * C2 + og] = ls0; s_rs[pg * C2 + og + 1] = ls1;
    s_rq[pg * C2 + og] = lq0; s_rq[pg * C2 + og + 1] = lq1;
    __syncthreads();
    if (t < C2) {
        float S = s_rs[t] + s_rs[C2 + t] + s_rs[2 * C2 + t] + s_rs[3 * C2 + t];
        float Q = s_rq[t] + s_rq[C2 + t] + s_rq[2 * C2 + t] + s_rq[3 * C2 + t];
        int b = v & (NBUCK - 1);
        atomicAdd(&g_sumB[b][C1 + t], (double)S);
        atomicAdd(&g_sqB [b][C1 + t], (double)Q);
    }
}

// ---------------- pass 3: 8 groups x 64 threads; register stats; end-flush --------
// phys channel map: true o = 16*ogi + 4q + r  <->  phys = 32q + 4*ogi + r
#define HB_S   68
#define RED_S  68          // per-ogi stride in red (bank-spread)
#define G_HB   0           // 40*68 = 2720
#define G_KEEP 2720        // 40
#define G_MM   2760        // 512
#define G_M2   3272        // 64
#define G_B    3336        // 128
#define G_RED  3464        // 2 warps * 8 ogi * RED_S = 1088
#define G_SS   4552        // 128 (true-channel running sums)
#define G_SQ   4680        // 128
#define GRPSZ  4816
#define F_SC   16384
#define F_SH   16448
#define F_GRP  16512
#define SM2_BYTES ((F_GRP + NGRP * GRPSZ) * 4)

#define GBAR() asm volatile("bar.sync %0, %1;" :: "r"(gi + 1), "r"(GT) : "memory")

__global__ void __launch_bounds__(T2V, 1) k_vfe2(const float4* __restrict__ Wd4,
                                                 const float*  __restrict__ bd, int V) {
    extern __shared__ float sm2[];
    float* s_wd = sm2;                 // [128][128] phys-permuted
    float* s_sc = sm2 + F_SC;
    float* s_sh = sm2 + F_SH;

    int t = threadIdx.x;

    // ---- one-time staging ----
    for (int i = t; i < A2C * 32; i += T2V) {
        int k = i >> 5, c = i & 31;
        float4 wv = Wd4[i];
        *(float4*)(s_wd + k * A2C + (c & 3) * 32 + (c >> 2) * 4) = wv;
    }
    if (t < C2) { s_sc[t] = g_scale[C1 + t]; s_sh[t] = g_shift[C1 + t]; }

    int gi = t >> 6;                   // group 0..7 (warp-uniform)
    int lt = t & 63;

    float* buf    = sm2 + F_GRP + gi * GRPSZ + G_HB;
    float* s_keep = sm2 + F_GRP + gi * GRPSZ + G_KEEP;
    float* s_mm   = sm2 + F_GRP + gi * GRPSZ + G_MM;
    float* s_m2   = sm2 + F_GRP + gi * GRPSZ + G_M2;
    float* s_B    = sm2 + F_GRP + gi * GRPSZ + G_B;
    float* s_red  = sm2 + F_GRP + gi * GRPSZ + G_RED;
    float* s_Ss   = sm2 + F_GRP + gi * GRPSZ + G_SS;
    float* s_Sq   = sm2 + F_GRP + gi * GRPSZ + G_SQ;

    // zero running sums + hb pad rows (one-time; nothing clobbers pads now)
    if (lt < 64) {
        s_Ss[lt] = 0.f; s_Ss[lt + 64] = 0.f;
        s_Sq[lt] = 0.f; s_Sq[lt + 64] = 0.f;
    }
    for (int j = lt; j < 5 * HB_S; j += GT) buf[35 * HB_S + j] = 0.f;
    __syncthreads();

    int ogi  = lt & 7;                 // 16 outputs: o in [16*ogi, 16*ogi+16)
    int slot = lt >> 3;                // 0..7
    int wrp  = lt >> 5;                // 0 or 1
    int lane = lt & 31;

    for (int v = blockIdx.x * NGRP + gi; v < V; v += NSTREAM) {
        const float* keepg = g_keep + (size_t)v * PP;

        // ---- phase 1: load h2 + BN2 + relu + keep-fold -> hb; raw min/max ----
        {
            if (lt < 40) s_keep[lt] = (lt < PP) ? keepg[lt] : 0.f;
            float rmx[4], rmn[4];
            #pragma unroll
            for (int q = 0; q < 4; q++) { rmx[q] = -3.4e38f; rmn[q] = 3.4e38f; }
            const float4* h2g4 = (const float4*)(g_h2 + (size_t)v * (PP * C2));
            int c4 = (lt & 15) * 4;
            float4 scv = *(const float4*)(s_sc + c4);
            float4 shv = *(const float4*)(s_sh + c4);
            for (int i = lt; i < (PP * C2) / 4; i += GT) {
                float4 h = h2g4[i];
                int p = i >> 4;
                float kp = keepg[p];
                rmx[0] = fmaxf(rmx[0], h.x); rmn[0] = fminf(rmn[0], h.x);
                rmx[1] = fmaxf(rmx[1], h.y); rmn[1] = fminf(rmn[1], h.y);
                rmx[2] = fmaxf(rmx[2], h.z); rmn[2] = fminf(rmn[2], h.z);
                rmx[3] = fmaxf(rmx[3], h.w); rmn[3] = fminf(rmn[3], h.w);
                float4 o;
                o.x = fmaxf(fmaf(h.x, scv.x, shv.x), 0.f) * kp;
                o.y = fmaxf(fmaf(h.y, scv.y, shv.y), 0.f) * kp;
                o.z = fmaxf(fmaf(h.z, scv.z, shv.z), 0.f) * kp;
                o.w = fmaxf(fmaf(h.w, scv.w, shv.w), 0.f) * kp;
                *(float4*)(buf + p * HB_S + c4) = o;
            }
            float* mm = s_mm + (lt >> 4) * 128 + (lt & 15) * 8;
            #pragma unroll
            for (int q = 0; q < 4; q++) { mm[q] = rmx[q]; mm[4 + q] = rmn[q]; }
        }
        GBAR();

        // ---- phase 2: finalize m2 (max over p of relu(bn(h2)), unmasked) ----
        if (lt < C2) {
            int cg = lt >> 2, r = lt & 3;
            float MX = -3.4e38f, MN = 3.4e38f;
            #pragma unroll
            for (int w = 0; w < 4; w++) {
                MX = fmaxf(MX, s_mm[w * 128 + cg * 8 + r]);
                MN = fminf(MN, s_mm[w * 128 + cg * 8 + 4 + r]);
            }
            float sc = s_sc[lt];
            float sel = (sc >= 0.f) ? MX : MN;
            s_m2[lt] = fmaxf(fmaf(sel, sc, s_sh[lt]), 0.f);
        }
        GBAR();

        // ---- phase 3: B vector then GEMM ----
        {
            ull b = 0ULL;
            #pragma unroll 8
            for (int k = 0; k < 64; k++) {
                float m = s_m2[k];
                ull w = *(const ull*)(s_wd + (64 + k) * A2C + 2 * lt);
                fma2(b, pack2(m, m), w);
            }
            *(ull*)(s_B + 2 * lt) = b;
        }

        ull acc[5][8];
        #pragma unroll
        for (int j = 0; j < 5; j++)
            #pragma unroll
            for (int jj = 0; jj < 8; jj++) acc[j][jj] = 0ULL;

        const float* hbs = buf + slot * HB_S;
        #pragma unroll 2
        for (int k = 0; k < 64; k++) {
            const ulonglong2* wk = (const ulonglong2*)(s_wd + k * A2C);
            ulonglong2 w0 = wk[ogi], w1 = wk[8 + ogi];
            ulonglong2 w2 = wk[16 + ogi], w3 = wk[24 + ogi];
            #pragma unroll
            for (int j = 0; j < 5; j++) {
                float a = hbs[j * 8 * HB_S + k];
                ull ap = pack2(a, a);
                fma2(acc[j][0], ap, w0.x); fma2(acc[j][1], ap, w0.y);
                fma2(acc[j][2], ap, w1.x); fma2(acc[j][3], ap, w1.y);
                fma2(acc[j][4], ap, w2.x); fma2(acc[j][5], ap, w2.y);
                fma2(acc[j][6], ap, w3.x); fma2(acc[j][7], ap, w3.y);
            }
        }
        GBAR();   // hb reads + B writes complete

        // ---- phase 4: epilogue + register stats + warp shfl reduce ----
        {
            float kp[5]; bool val[5];
            #pragma unroll
            for (int j = 0; j < 5; j++) {
                int p = slot + 8 * j;
                val[j] = (p < PP);
                kp[j]  = val[j] ? s_keep[p] : 0.f;
            }
            #pragma unroll
            for (int q = 0; q < 4; q++) {
                ull Bx  = *(const ull*)(s_B + q * 32 + ogi * 4);
                ull By  = *(const ull*)(s_B + q * 32 + ogi * 4 + 2);
                ull bdx = ((const ull*)bd)[8 * ogi + 2 * q];
                ull bdy = ((const ull*)bd)[8 * ogi + 2 * q + 1];
                float S[4] = {0, 0, 0, 0}, Q[4] = {0, 0, 0, 0};
                float MX[4], MN[4];
                #pragma unroll
                for (int e = 0; e < 4; e++) { MX[e] = -3.4e38f; MN[e] = 3.4e38f; }
                #pragma unroll
                for (int j = 0; j < 5; j++) {
                    ull kpp = pack2(kp[j], kp[j]);
                    fma2(acc[j][2 * q],     Bx, kpp); add2(acc[j][2 * q],     bdx);
                    fma2(acc[j][2 * q + 1], By, kpp); add2(acc[j][2 * q + 1], bdy);
                    if (val[j]) {
                        float2 r0 = unpack2(acc[j][2 * q]);
                        float2 r1 = unpack2(acc[j][2 * q + 1]);
                        S[0] += r0.x; Q[0] = fmaf(r0.x, r0.x, Q[0]);
                        MX[0] = fmaxf(MX[0], r0.x); MN[0] = fminf(MN[0], r0.x);
                        S[1] += r0.y; Q[1] = fmaf(r0.y, r0.y, Q[1]);
                        MX[1] = fmaxf(MX[1], r0.y); MN[1] = fminf(MN[1], r0.y);
                        S[2] += r1.x; Q[2] = fmaf(r1.x, r1.x, Q[2]);
                        MX[2] = fmaxf(MX[2], r1.x); MN[2] = fminf(MN[2], r1.x);
                        S[3] += r1.y; Q[3] = fmaf(r1.y, r1.y, Q[3]);
                        MX[3] = fmaxf(MX[3], r1.y); MN[3] = fminf(MN[3], r1.y);
                    }
                }
                #pragma unroll
                for (int e = 0; e < 4; e++) {
                    S[e]  += __shfl_xor_sync(0xffffffffu, S[e],  8);
                    S[e]  += __shfl_xor_sync(0xffffffffu, S[e],  16);
                    Q[e]  += __shfl_xor_sync(0xffffffffu, Q[e],  8);
                    Q[e]  += __shfl_xor_sync(0xffffffffu, Q[e],  16);
                    MX[e]  = fmaxf(MX[e], __shfl_xor_sync(0xffffffffu, MX[e], 8));
                    MX[e]  = fmaxf(MX[e], __shfl_xor_sync(0xffffffffu, MX[e], 16));
                    MN[e]  = fminf(MN[e], __shfl_xor_sync(0xffffffffu, MN[e], 8));
                    MN[e]  = fminf(MN[e], __shfl_xor_sync(0xffffffffu, MN[e], 16));
                }
                if (lane < 8) {
                    float* rd = s_red + wrp * 8 * RED_S + ogi * RED_S + q * 16;
                    #pragma unroll
                    for (int e = 0; e < 4; e++) {
                        rd[e * 4 + 0] = S[e];
                        rd[e * 4 + 1] = Q[e];
                        rd[e * 4 + 2] = MX[e];
                        rd[e * 4 + 3] = MN[e];
                    }
                }
            }
        }
        GBAR();

        // ---- phase 5: warp 0 combines both warps; update running sums; store mx/mn
        if (wrp == 0) {
            int cogi = lane & 7, cq = lane >> 3;     // 32 lanes = 8 ogi x 4 q
            const float* r0 = s_red + cogi * RED_S + cq * 16;
            const float* r1 = r0 + 8 * RED_S;
            float4 mxv, mnv;
            float* mxp = &mxv.x; float* mnp = &mnv.x;
            #pragma unroll
            for (int e = 0; e < 4; e++) {
                float S  = r0[e * 4 + 0] + r1[e * 4 + 0];
                float Q  = r0[e * 4 + 1] + r1[e * 4 + 1];
                float MX = fmaxf(r0[e * 4 + 2], r1[e * 4 + 2]);
                float MN = fminf(r0[e * 4 + 3], r1[e * 4 + 3]);
                int o = 16 * cogi + 4 * cq + e;      // true channel
                s_Ss[o] += S; s_Sq[o] += Q;
                mxp[e] = MX; mnp[e] = MN;
            }
            int ob = 16 * cogi + 4 * cq;
            *(float4*)(g_max3 + (size_t)v * C3 + ob) = mxv;
            *(float4*)(g_min3 + (size_t)v * C3 + ob) = mnv;
        }
        GBAR();
    }

    // ---- end: flush running stats once per group ----
    GBAR();
    {
        int b = (blockIdx.x * NGRP + gi) & (NBUCK - 1);
        int o0 = lt, o1 = lt + 64;
        atomicAdd(&g_sumB[b][C1 + C2 + o0], (double)s_Ss[o0]);
        atomicAdd(&g_sqB [b][C1 + C2 + o0], (double)s_Sq[o0]);
        atomicAdd(&g_sumB[b][C1 + C2 + o1], (double)s_Ss[o1]);
        atomicAdd(&g_sqB [b][C1 + C2 + o1], (double)s_Sq[o1]);
    }
}

// ---------------- pass 4: BN3 + relu + max (via max/min) + scatter-add ------------
__global__ void k_scatter(const int* __restrict__ coord, float* __restrict__ out, int V) {
    int v = blockIdx.x;
    if (v >= V) return;
    int u = threadIdx.x;
    float sc = g_scale[C1 + C2 + u];
    float sh = g_shift[C1 + C2 + u];
    float h  = (sc >= 0.0f) ? g_max3[(size_t)v * C3 + u] : g_min3[(size_t)v * C3 + u];
    float val = fmaxf(fmaf(h, sc, sh), 0.0f);
    int cz = coord[v * 3 + 0];
    int cy = coord[v * 3 + 1];
    int cx = coord[v * 3 + 2];
    size_t off = (size_t)u * (DD * HH * WWG) + (size_t)cz * (HH * WWG) + (size_t)cy * WWG + cx;
    atomicAdd(out + off, val);
}

// ---------------- launch -----------------------------------------------------------
extern "C" void kernel_launch(void* const* d_in, const int* in_sizes, int n_in,
                              void* d_out, int out_size) {
    const float* x     = (const float*)d_in[0];
    const int*   coord = (const int*)  d_in[1];
    const float* W1 = (const float*)d_in[2];
    const float* b1 = (const float*)d_in[3];
    const float* g1 = (const float*)d_in[4];
    const float* be1= (const float*)d_in[5];
    const float* W2 = (const float*)d_in[6];
    const float* b2 = (const float*)d_in[7];
    const float* g2 = (const float*)d_in[8];
    const float* be2= (const float*)d_in[9];
    const float* Wd = (const float*)d_in[10];
    const float* bd = (const float*)d_in[11];
    const float* gd = (const float*)d_in[12];
    const float* bed= (const float*)d_in[13];

    int V = in_sizes[1] / 3;
    if (V > VMAX) V = VMAX;
    double invN = 1.0 / ((double)V * PP);

    cudaFuncSetAttribute(k_vfe2, cudaFuncAttributeMaxDynamicSharedMemorySize, SM2_BYTES);

    cudaMemsetAsync(d_out, 0, (size_t)out_size * sizeof(float), 0);
    k_zero_stats<<<32, 256>>>();
    k_stats1<<<592, 256>>>(x, W1, b1, V);
    k_finalize<<<1, 256>>>(g1, be1, 0, C1, invN);
    k_vfe1<<<V, 128>>>(x, W1, b1, W2, b2, V);
    k_finalize<<<1, 256>>>(g2, be2, C1, C2, invN);
    k_vfe2<<<GRID2, T2V, SM2_BYTES>>>((const float4*)Wd, bd, V);
    k_finalize<<<1, 256>>>(gd, bed, C1 + C2, C3, invN);
    k_scatter<<<V, 128>>>(coord, (float*)d_out, V);
}